// round 11
// baseline (speedup 1.0000x reference)
#include <cuda_runtime.h>
#include <cuda_bf16.h>
#include <math.h>
#include <stdint.h>

// Shapes (fixed for this problem)
#define BATCH 16
#define SEQL  128
#define DIM   768
#define NH1   770
#define NOUT  40
#define NPAIR 3405
#define LP1   129     // L+1 rows per batch in hidden_states
#define PST   772     // padded row stride for P/Q (float4-aligned)

// Scratch: P = X @ W1i, Q = X @ W1j (X = hidden[:,1:129,:] flattened, 2048 rows).
// Columns 770..771 are written as zeros (B operand cols >= 770 loaded as 0).
__device__ float g_P[(size_t)BATCH * SEQL * PST + 64];
__device__ float g_Q[(size_t)BATCH * SEQL * PST + 64];

// ---------------------------------------------------------------------------
// Helpers: smem addr, ldmatrix, bf16 mma, bf16 two-term split.
// ---------------------------------------------------------------------------
__device__ __forceinline__ uint32_t smem_u32(const void* p) {
    uint32_t a;
    asm("{ .reg .u64 t; cvta.to.shared.u64 t, %1; cvt.u32.u64 %0, t; }" : "=r"(a) : "l"(p));
    return a;
}
#define LDM_X4(r0, r1, r2, r3, addr) \
    asm volatile("ldmatrix.sync.aligned.m8n8.x4.shared.b16 {%0,%1,%2,%3}, [%4];" \
                 : "=r"(r0), "=r"(r1), "=r"(r2), "=r"(r3) : "r"(addr))

__device__ __forceinline__ void mma_bf16(float* d, const uint32_t* a,
                                         uint32_t b0, uint32_t b1) {
    asm volatile(
        "mma.sync.aligned.m16n8k16.row.col.f32.bf16.bf16.f32 "
        "{%0,%1,%2,%3}, {%4,%5,%6,%7}, {%8,%9}, {%0,%1,%2,%3};\n"
        : "+f"(d[0]), "+f"(d[1]), "+f"(d[2]), "+f"(d[3])
        : "r"(a[0]), "r"(a[1]), "r"(a[2]), "r"(a[3]), "r"(b0), "r"(b1));
}
// Split x0,x1 into (hi word, lo word), each word = 2 packed bf16.
__device__ __forceinline__ void split2(float x0, float x1, uint32_t& hw, uint32_t& lw) {
    __nv_bfloat16 h0 = __float2bfloat16_rn(x0);
    __nv_bfloat16 h1 = __float2bfloat16_rn(x1);
    float l0 = x0 - __bfloat162float(h0);
    float l1 = x1 - __bfloat162float(h1);
    __nv_bfloat16 g0 = __float2bfloat16_rn(l0);
    __nv_bfloat16 g1 = __float2bfloat16_rn(l1);
    hw = (uint32_t)__bfloat16_as_ushort(h0) | ((uint32_t)__bfloat16_as_ushort(h1) << 16);
    lw = (uint32_t)__bfloat16_as_ushort(g0) | ((uint32_t)__bfloat16_as_ushort(g1) << 16);
}

// ---------------------------------------------------------------------------
// Kernel 1 (unchanged from R9 — measured ~55us, HMMA-pipe-bound):
// 2048 x 896(pad of 770) x 768 GEMM, bf16 m16n8k16 + ldmatrix, 2-term split.
// ---------------------------------------------------------------------------
#define G_BK  32
#define G_NKT (DIM / G_BK)   // 24
#define RS    80             // smem row stride in bytes
#define AHI_O 0
#define ALO_O (128 * RS)     // 10240
#define BHI_O (2 * 128 * RS) // 20480
#define BLO_O (3 * 128 * RS) // 30720

__global__ __launch_bounds__(256, 2)
void gemm1_mma(const float* __restrict__ hidden, const float* __restrict__ W1) {
    __shared__ __align__(16) unsigned char smbuf[4 * 128 * RS];  // 40960 B
    const uint32_t sb = smem_u32(smbuf);

    const int tid = threadIdx.x;
    const int wid = tid >> 5;
    const int lid = tid & 31;
    const int grp = lid >> 2;   // 0..7
    const int tig = lid & 3;    // 0..3
    const int wm  = wid & 3;    // warp M index (32 rows)
    const int wn  = wid >> 2;   // warp N index (64 cols)

    const int n0 = blockIdx.x * 128;
    const int m0 = blockIdx.y * 128;
    const float* W = W1 + (size_t)blockIdx.z * DIM * NH1;
    float* Cout = (blockIdx.z == 0) ? g_P : g_Q;

    float acc[2][8][4];
    #pragma unroll
    for (int mf = 0; mf < 2; mf++)
        #pragma unroll
        for (int nf = 0; nf < 8; nf++)
            #pragma unroll
            for (int c = 0; c < 4; c++) acc[mf][nf][c] = 0.f;

    const int a_k4 = tid & 7;
    const int a_r0 = tid >> 3;
    const int bb   = m0 >> 7;
    const float* abase = hidden + ((size_t)bb * LP1 + 1) * DIM + a_k4 * 4;

    const int  b_nl   = tid & 127;
    const int  b_kh   = (tid >> 7) * 16;
    const int  ncol   = n0 + b_nl;
    const bool bok    = ncol < NH1;
    const float* bcol = W + (bok ? ncol : 0);

    const int a_lrow = lid & 15;
    const int a_lk   = (lid >> 4) << 3;
    const int b_lrow = (lid & 7) + ((lid >> 4) << 3);
    const int b_lk   = ((lid >> 3) & 1) << 3;

    for (int kt = 0; kt < G_NKT; kt++) {
        const int gk0 = kt * G_BK;
        #pragma unroll
        for (int p = 0; p < 4; p++) {
            const int row = a_r0 + 32 * p;
            float4 v = *(const float4*)(abase + (size_t)row * DIM + gk0);
            uint32_t h01, l01, h23, l23;
            split2(v.x, v.y, h01, l01);
            split2(v.z, v.w, h23, l23);
            const uint32_t ro = row * RS + a_k4 * 8;
            *(uint32_t*)(smbuf + AHI_O + ro)     = h01;
            *(uint32_t*)(smbuf + AHI_O + ro + 4) = h23;
            *(uint32_t*)(smbuf + ALO_O + ro)     = l01;
            *(uint32_t*)(smbuf + ALO_O + ro + 4) = l23;
        }
        #pragma unroll
        for (int u = 0; u < 16; u += 2) {
            const int k = b_kh + u;
            float x0 = bok ? bcol[(size_t)(gk0 + k)     * NH1] : 0.f;
            float x1 = bok ? bcol[(size_t)(gk0 + k + 1) * NH1] : 0.f;
            uint32_t hw, lw;
            split2(x0, x1, hw, lw);
            const uint32_t ro = b_nl * RS + k * 2;
            *(uint32_t*)(smbuf + BHI_O + ro) = hw;
            *(uint32_t*)(smbuf + BLO_O + ro) = lw;
        }
        __syncthreads();

        #pragma unroll
        for (int h = 0; h < 2; h++) {
            const int ks = h * 16;
            uint32_t ah[2][4], al[2][4];
            #pragma unroll
            for (int mf = 0; mf < 2; mf++) {
                const uint32_t ad = sb + (wm * 32 + mf * 16 + a_lrow) * RS
                                       + (ks + a_lk) * 2;
                LDM_X4(ah[mf][0], ah[mf][1], ah[mf][2], ah[mf][3], ad + AHI_O);
                LDM_X4(al[mf][0], al[mf][1], al[mf][2], al[mf][3], ad + ALO_O);
            }
            #pragma unroll
            for (int p = 0; p < 4; p++) {
                const uint32_t bd = sb + (wn * 64 + p * 16 + b_lrow) * RS
                                       + (ks + b_lk) * 2;
                uint32_t bh[4], bl[4];
                LDM_X4(bh[0], bh[1], bh[2], bh[3], bd + BHI_O);
                LDM_X4(bl[0], bl[1], bl[2], bl[3], bd + BLO_O);
                #pragma unroll
                for (int q = 0; q < 2; q++) {
                    const int nf = 2 * p + q;
                    #pragma unroll
                    for (int mf = 0; mf < 2; mf++) {
                        mma_bf16(acc[mf][nf], ah[mf], bh[2*q], bh[2*q+1]);
                        mma_bf16(acc[mf][nf], ah[mf], bl[2*q], bl[2*q+1]);
                        mma_bf16(acc[mf][nf], al[mf], bh[2*q], bh[2*q+1]);
                    }
                }
            }
        }
        __syncthreads();
    }

    #pragma unroll
    for (int mf = 0; mf < 2; mf++) {
        const int row = m0 + wm * 32 + mf * 16 + grp;
        #pragma unroll
        for (int nf = 0; nf < 8; nf++) {
            const int nn = n0 + wn * 64 + nf * 8 + tig * 2;
            if (nn + 1 < PST) {
                float* p0 = Cout + (size_t)row * PST + nn;
                float* p1 = Cout + (size_t)(row + 8) * PST + nn;
                *(float2*)p0 = make_float2(acc[mf][nf][0], acc[mf][nf][1]);
                *(float2*)p1 = make_float2(acc[mf][nf][2], acc[mf][nf][3]);
            }
        }
    }
}

// ---------------------------------------------------------------------------
// Kernel 2 (NEW: tensorized): per (batch, 128-pair chunk):
//   Ht[r][k] = relu(P[vi_r][k] + Q[vj_r][k] + ind_r*w1c[k] + b1[k])  (bf16 split)
//   logits   = Ht @ W2 + b2 via mma.m16n8k16 (3-term split), fused log_softmax.
// 256 thr = 8 warps; warp w owns pairs 16w..16w+15 (one m16 tile) x 40 outs
// (5 n8 tiles). K chunks of 32 (25 chunks cover 770, rest zero-padded).
// Same RS=80 / ldmatrix lane maps as gemm1 (validated at rel_err 3.7e-7).
// ---------------------------------------------------------------------------
#define SP_CH   32
#define SP_NCH  25
#define AHT_HI  0
#define AHT_LO  (128 * RS)            // 10240
#define W2H_O   (2 * 128 * RS)        // 20480
#define W2L_O   (W2H_O + 48 * RS)     // 24320
#define SP_SMEM (W2L_O + 48 * RS)     // 28160 B

__global__ __launch_bounds__(256, 2)
void span_head_tensor(const float* __restrict__ W1, const float* __restrict__ bias1,
                      const float* __restrict__ W2, const float* __restrict__ bias2,
                      const int* __restrict__ spans, float* __restrict__ out) {
    __shared__ __align__(16) unsigned char smbuf[SP_SMEM];
    __shared__ int   s_ri[128];
    __shared__ int   s_rj[128];
    __shared__ float s_ind[128];
    const uint32_t sb = smem_u32(smbuf);

    const int b   = blockIdx.y;
    const int p0  = blockIdx.x * 128;
    const int tid = threadIdx.x;
    const int wid = tid >> 5;
    const int lid = tid & 31;
    const int grp = lid >> 2;   // 0..7
    const int tig = lid & 3;    // 0..3

    const float* w1c = W1 + (size_t)2 * DIM * NH1;  // row 1536 of W1

    // Analytic pair decode (nonzero order of (j>=i, j-i<30) band, L=128).
    if (tid < 128) {
        int p  = p0 + tid;
        int pc = (p < NPAIR) ? p : (NPAIR - 1);
        int i, j;
        if (pc < 2970) {
            i = pc / 30;
            j = i + (pc - 30 * i);
        } else {
            int q = pc - 2970;
            int d = (int)(29.5f - sqrtf(870.25f - 2.0f * (float)q));
            while ((d + 1) * (58 - d) / 2 <= q) d++;
            while (d * (59 - d) / 2 > q) d--;
            i = 99 + d;
            j = i + (q - d * (59 - d) / 2);
        }
        float ind = 0.f;
        if (p < NPAIR) {
            int s = spans[b*2 + 0];
            int e = spans[b*2 + 1];
            if (i == s && j == e)      ind = 2.f;
            else if (i >= s && j <= e) ind = 1.f;
        }
        s_ri[tid]  = (b * SEQL + i) * PST;
        s_rj[tid]  = (b * SEQL + j) * PST;
        s_ind[tid] = ind;
    }
    // Zero W2 smem pad rows (n = 40..47) once; never overwritten afterwards.
    if (tid < 128) {
        int buf = tid >> 6;                 // 0: hi, 1: lo
        int t2  = tid & 63;
        int row = 40 + (t2 >> 3);
        int w   = t2 & 7;
        *(uint64_t*)(smbuf + (buf ? W2L_O : W2H_O) + row * RS + w * 8) = 0ull;
    }
    __syncthreads();

    const int g_kq = tid & 7;    // k quad within 32-wide slab
    const int g_r0 = tid >> 3;   // pair rows g_r0 + 32w
    const int a_lrow = lid & 15;
    const int a_lk   = (lid >> 4) << 3;
    const int b_lrow = (lid & 7) + ((lid >> 4) << 3);
    const int b_lk   = ((lid >> 3) & 1) << 3;

    float acc[5][4];
    #pragma unroll
    for (int nf = 0; nf < 5; nf++)
        #pragma unroll
        for (int c = 0; c < 4; c++) acc[nf][c] = 0.f;

    for (int ch = 0; ch < SP_NCH; ch++) {
        const int k0 = ch * SP_CH;
        // ---- W2 tile: 32k x 40n fp32 -> split bf16, stored [n][k] ----
        #pragma unroll
        for (int u = 0; u < 5; u++) {
            int idx = u * 256 + tid;        // 0..1279
            int k   = idx / 40;
            int n   = idx - 40 * k;
            float x = (k0 + k < NH1) ? W2[(size_t)(k0 + k) * NOUT + n] : 0.f;
            __nv_bfloat16 h = __float2bfloat16_rn(x);
            __nv_bfloat16 l = __float2bfloat16_rn(x - __bfloat162float(h));
            uint32_t off = n * RS + k * 2;
            *(unsigned short*)(smbuf + W2H_O + off) = __bfloat16_as_ushort(h);
            *(unsigned short*)(smbuf + W2L_O + off) = __bfloat16_as_ushort(l);
        }
        // ---- Ht tile: gather P/Q, relu, split, store [pair][k] ----
        const int kb = k0 + g_kq * 4;
        if (kb < PST) {
            float4 c1, c2;
            if (kb + 3 < NH1) {
                c1 = *(const float4*)(w1c + kb);
                c2 = *(const float4*)(bias1 + kb);
            } else {
                c1.x = (kb+0 < NH1) ? w1c[kb+0] : 0.f;
                c1.y = (kb+1 < NH1) ? w1c[kb+1] : 0.f;
                c1.z = (kb+2 < NH1) ? w1c[kb+2] : 0.f;
                c1.w = (kb+3 < NH1) ? w1c[kb+3] : 0.f;
                c2.x = (kb+0 < NH1) ? bias1[kb+0] : 0.f;
                c2.y = (kb+1 < NH1) ? bias1[kb+1] : 0.f;
                c2.z = (kb+2 < NH1) ? bias1[kb+2] : 0.f;
                c2.w = (kb+3 < NH1) ? bias1[kb+3] : 0.f;
            }
            #pragma unroll
            for (int w = 0; w < 4; w++) {
                int r = g_r0 + w * 32;
                float4 p4 = *(const float4*)(g_P + s_ri[r] + kb);
                float4 q4 = *(const float4*)(g_Q + s_rj[r] + kb);
                float ind = s_ind[r];
                float v0 = fmaxf(fmaf(ind, c1.x, p4.x + q4.x + c2.x), 0.f);
                float v1 = fmaxf(fmaf(ind, c1.y, p4.y + q4.y + c2.y), 0.f);
                float v2 = fmaxf(fmaf(ind, c1.z, p4.z + q4.z + c2.z), 0.f);
                float v3 = fmaxf(fmaf(ind, c1.w, p4.w + q4.w + c2.w), 0.f);
                uint32_t hw0, lw0, hw1, lw1;
                split2(v0, v1, hw0, lw0);
                split2(v2, v3, hw1, lw1);
                uint32_t ro = r * RS + g_kq * 8;
                *(uint2*)(smbuf + AHT_HI + ro) = make_uint2(hw0, hw1);
                *(uint2*)(smbuf + AHT_LO + ro) = make_uint2(lw0, lw1);
            }
        } else {   // k >= 772: zero fill (never read P/Q pad)
            #pragma unroll
            for (int w = 0; w < 4; w++) {
                int r = g_r0 + w * 32;
                uint32_t ro = r * RS + g_kq * 8;
                *(uint2*)(smbuf + AHT_HI + ro) = make_uint2(0u, 0u);
                *(uint2*)(smbuf + AHT_LO + ro) = make_uint2(0u, 0u);
            }
        }
        __syncthreads();

        // ---- MMA: warp wid = pairs 16*wid..+15; 5 n8 tiles; 3 split terms ----
        #pragma unroll
        for (int h = 0; h < 2; h++) {
            const int ks = h * 16;
            uint32_t ah[4], al[4];
            const uint32_t ad = sb + (wid * 16 + a_lrow) * RS + (ks + a_lk) * 2;
            LDM_X4(ah[0], ah[1], ah[2], ah[3], ad + AHT_HI);
            LDM_X4(al[0], al[1], al[2], al[3], ad + AHT_LO);
            #pragma unroll
            for (int p = 0; p < 3; p++) {
                const uint32_t bd = sb + (p * 16 + b_lrow) * RS + (ks + b_lk) * 2;
                uint32_t bh[4], bl[4];
                LDM_X4(bh[0], bh[1], bh[2], bh[3], bd + W2H_O);
                LDM_X4(bl[0], bl[1], bl[2], bl[3], bd + W2L_O);
                const int nq = (p < 2) ? 2 : 1;   // tile 5 (cols 40..47) skipped
                #pragma unroll
                for (int q = 0; q < 2; q++) {
                    if (q >= nq) break;
                    const int nf = 2 * p + q;
                    mma_bf16(acc[nf], ah, bh[2*q], bh[2*q+1]);
                    mma_bf16(acc[nf], ah, bl[2*q], bl[2*q+1]);
                    mma_bf16(acc[nf], al, bh[2*q], bh[2*q+1]);
                }
            }
        }
        __syncthreads();
    }

    // ---- bias + log_softmax (4-lane butterfly over tig) + store ----
    float bb[10];
    #pragma unroll
    for (int nf = 0; nf < 5; nf++) {
        bb[2*nf + 0] = bias2[nf * 8 + tig * 2 + 0];
        bb[2*nf + 1] = bias2[nf * 8 + tig * 2 + 1];
    }

    #pragma unroll
    for (int rr = 0; rr < 2; rr++) {
        float l[10];
        #pragma unroll
        for (int nf = 0; nf < 5; nf++) {
            l[2*nf + 0] = acc[nf][2*rr + 0] + bb[2*nf + 0];
            l[2*nf + 1] = acc[nf][2*rr + 1] + bb[2*nf + 1];
        }
        float mx = l[0];
        #pragma unroll
        for (int j = 1; j < 10; j++) mx = fmaxf(mx, l[j]);
        mx = fmaxf(mx, __shfl_xor_sync(0xffffffffu, mx, 1));
        mx = fmaxf(mx, __shfl_xor_sync(0xffffffffu, mx, 2));
        float sm = 0.f;
        #pragma unroll
        for (int j = 0; j < 10; j++) sm += expf(l[j] - mx);
        sm += __shfl_xor_sync(0xffffffffu, sm, 1);
        sm += __shfl_xor_sync(0xffffffffu, sm, 2);
        float lse = mx + logf(sm);

        int p_row = p0 + wid * 16 + grp + 8 * rr;
        if (p_row < NPAIR) {
            float* op = out + ((size_t)b * NPAIR + p_row) * NOUT;
            #pragma unroll
            for (int nf = 0; nf < 5; nf++) {
                float2 v = make_float2(l[2*nf] - lse, l[2*nf + 1] - lse);
                *(float2*)(op + nf * 8 + tig * 2) = v;
            }
        }
    }
}

// ---------------------------------------------------------------------------
// Launch. Inputs (metadata order): hidden_states, pred_spans, token_num,
// span_available_indication_matrix, W1, b1, W2, b2. Output fp32 [16,3405,40].
// ---------------------------------------------------------------------------
extern "C" void kernel_launch(void* const* d_in, const int* in_sizes, int n_in,
                              void* d_out, int out_size) {
    const float* hidden = (const float*)d_in[0];
    const int*   spans  = (const int*)d_in[1];
    const float* W1 = (const float*)d_in[4];
    const float* b1 = (const float*)d_in[5];
    const float* W2 = (const float*)d_in[6];
    const float* b2 = (const float*)d_in[7];
    float* out = (float*)d_out;

    gemm1_mma<<<dim3(7, (BATCH * SEQL) / 128, 2), 256>>>(hidden, W1);
    span_head_tensor<<<dim3(27, BATCH), 256>>>(W1, b1, W2, b2, spans, out);
}

// round 12
// speedup vs baseline: 1.3836x; 1.3836x over previous
#include <cuda_runtime.h>
#include <cuda_bf16.h>
#include <math.h>
#include <stdint.h>

// Shapes (fixed for this problem)
#define BATCH 16
#define SEQL  128
#define DIM   768
#define NH1   770
#define NOUT  40
#define NPAIR 3405
#define LP1   129     // L+1 rows per batch in hidden_states
#define PST   772     // padded row stride for P/Q (float4-aligned)

// Scratch: P = X @ W1i, Q = X @ W1j (X = hidden[:,1:129,:] flattened, 2048 rows).
__device__ float g_P[(size_t)BATCH * SEQL * PST + 64];
__device__ float g_Q[(size_t)BATCH * SEQL * PST + 64];
// Precomputed split-bf16 W2, tile layout [chunk(25)][n(48)][kword(16)] (k pairs).
__device__ uint32_t g_W2h[25 * 768];
__device__ uint32_t g_W2l[25 * 768];

// ---------------------------------------------------------------------------
// Helpers
// ---------------------------------------------------------------------------
__device__ __forceinline__ uint32_t smem_u32(const void* p) {
    uint32_t a;
    asm("{ .reg .u64 t; cvta.to.shared.u64 t, %1; cvt.u32.u64 %0, t; }" : "=r"(a) : "l"(p));
    return a;
}
#define LDM_X4(r0, r1, r2, r3, addr) \
    asm volatile("ldmatrix.sync.aligned.m8n8.x4.shared.b16 {%0,%1,%2,%3}, [%4];" \
                 : "=r"(r0), "=r"(r1), "=r"(r2), "=r"(r3) : "r"(addr))

__device__ __forceinline__ void mma_bf16(float* d, const uint32_t* a,
                                         uint32_t b0, uint32_t b1) {
    asm volatile(
        "mma.sync.aligned.m16n8k16.row.col.f32.bf16.bf16.f32 "
        "{%0,%1,%2,%3}, {%4,%5,%6,%7}, {%8,%9}, {%0,%1,%2,%3};\n"
        : "+f"(d[0]), "+f"(d[1]), "+f"(d[2]), "+f"(d[3])
        : "r"(a[0]), "r"(a[1]), "r"(a[2]), "r"(a[3]), "r"(b0), "r"(b1));
}
__device__ __forceinline__ void split2(float x0, float x1, uint32_t& hw, uint32_t& lw) {
    __nv_bfloat16 h0 = __float2bfloat16_rn(x0);
    __nv_bfloat16 h1 = __float2bfloat16_rn(x1);
    float l0 = x0 - __bfloat162float(h0);
    float l1 = x1 - __bfloat162float(h1);
    __nv_bfloat16 g0 = __float2bfloat16_rn(l0);
    __nv_bfloat16 g1 = __float2bfloat16_rn(l1);
    hw = (uint32_t)__bfloat16_as_ushort(h0) | ((uint32_t)__bfloat16_as_ushort(h1) << 16);
    lw = (uint32_t)__bfloat16_as_ushort(g0) | ((uint32_t)__bfloat16_as_ushort(g1) << 16);
}

// ---------------------------------------------------------------------------
// Kernel 0: one-time W2 split. word idx = ch*768 + n*16 + kw, k = ch*32+2*kw.
// Rows n>=40 and k>=770 are zeros (kills the mma pad columns).
// ---------------------------------------------------------------------------
__global__ void prep_w2(const float* __restrict__ W2) {
    int idx = blockIdx.x * 256 + threadIdx.x;
    if (idx >= 25 * 768) return;
    int ch = idx / 768, rem = idx - ch * 768;
    int n = rem >> 4, kw = rem & 15;
    int k = ch * 32 + kw * 2;
    float x0 = 0.f, x1 = 0.f;
    if (n < NOUT) {
        if (k     < NH1) x0 = W2[(size_t)k       * NOUT + n];
        if (k + 1 < NH1) x1 = W2[(size_t)(k + 1) * NOUT + n];
    }
    uint32_t hw, lw;
    split2(x0, x1, hw, lw);
    g_W2h[idx] = hw;
    g_W2l[idx] = lw;
}

// ---------------------------------------------------------------------------
// Kernel 1 (unchanged from R9 — measured ~55us, HMMA-pipe-bound):
// 2048 x 896(pad of 770) x 768 GEMM, bf16 m16n8k16 + ldmatrix, 2-term split.
// ---------------------------------------------------------------------------
#define G_BK  32
#define G_NKT (DIM / G_BK)   // 24
#define RS    80             // smem row stride in bytes
#define AHI_O 0
#define ALO_O (128 * RS)
#define BHI_O (2 * 128 * RS)
#define BLO_O (3 * 128 * RS)

__global__ __launch_bounds__(256, 2)
void gemm1_mma(const float* __restrict__ hidden, const float* __restrict__ W1) {
    __shared__ __align__(16) unsigned char smbuf[4 * 128 * RS];  // 40960 B
    const uint32_t sb = smem_u32(smbuf);

    const int tid = threadIdx.x;
    const int wid = tid >> 5;
    const int lid = tid & 31;
    const int grp = lid >> 2;
    const int tig = lid & 3;
    const int wm  = wid & 3;
    const int wn  = wid >> 2;

    const int n0 = blockIdx.x * 128;
    const int m0 = blockIdx.y * 128;
    const float* W = W1 + (size_t)blockIdx.z * DIM * NH1;
    float* Cout = (blockIdx.z == 0) ? g_P : g_Q;

    float acc[2][8][4];
    #pragma unroll
    for (int mf = 0; mf < 2; mf++)
        #pragma unroll
        for (int nf = 0; nf < 8; nf++)
            #pragma unroll
            for (int c = 0; c < 4; c++) acc[mf][nf][c] = 0.f;

    const int a_k4 = tid & 7;
    const int a_r0 = tid >> 3;
    const int bb   = m0 >> 7;
    const float* abase = hidden + ((size_t)bb * LP1 + 1) * DIM + a_k4 * 4;

    const int  b_nl   = tid & 127;
    const int  b_kh   = (tid >> 7) * 16;
    const int  ncol   = n0 + b_nl;
    const bool bok    = ncol < NH1;
    const float* bcol = W + (bok ? ncol : 0);

    const int a_lrow = lid & 15;
    const int a_lk   = (lid >> 4) << 3;
    const int b_lrow = (lid & 7) + ((lid >> 4) << 3);
    const int b_lk   = ((lid >> 3) & 1) << 3;

    for (int kt = 0; kt < G_NKT; kt++) {
        const int gk0 = kt * G_BK;
        #pragma unroll
        for (int p = 0; p < 4; p++) {
            const int row = a_r0 + 32 * p;
            float4 v = *(const float4*)(abase + (size_t)row * DIM + gk0);
            uint32_t h01, l01, h23, l23;
            split2(v.x, v.y, h01, l01);
            split2(v.z, v.w, h23, l23);
            const uint32_t ro = row * RS + a_k4 * 8;
            *(uint32_t*)(smbuf + AHI_O + ro)     = h01;
            *(uint32_t*)(smbuf + AHI_O + ro + 4) = h23;
            *(uint32_t*)(smbuf + ALO_O + ro)     = l01;
            *(uint32_t*)(smbuf + ALO_O + ro + 4) = l23;
        }
        #pragma unroll
        for (int u = 0; u < 16; u += 2) {
            const int k = b_kh + u;
            float x0 = bok ? bcol[(size_t)(gk0 + k)     * NH1] : 0.f;
            float x1 = bok ? bcol[(size_t)(gk0 + k + 1) * NH1] : 0.f;
            uint32_t hw, lw;
            split2(x0, x1, hw, lw);
            const uint32_t ro = b_nl * RS + k * 2;
            *(uint32_t*)(smbuf + BHI_O + ro) = hw;
            *(uint32_t*)(smbuf + BLO_O + ro) = lw;
        }
        __syncthreads();

        #pragma unroll
        for (int h = 0; h < 2; h++) {
            const int ks = h * 16;
            uint32_t ah[2][4], al[2][4];
            #pragma unroll
            for (int mf = 0; mf < 2; mf++) {
                const uint32_t ad = sb + (wm * 32 + mf * 16 + a_lrow) * RS
                                       + (ks + a_lk) * 2;
                LDM_X4(ah[mf][0], ah[mf][1], ah[mf][2], ah[mf][3], ad + AHI_O);
                LDM_X4(al[mf][0], al[mf][1], al[mf][2], al[mf][3], ad + ALO_O);
            }
            #pragma unroll
            for (int p = 0; p < 4; p++) {
                const uint32_t bd = sb + (wn * 64 + p * 16 + b_lrow) * RS
                                       + (ks + b_lk) * 2;
                uint32_t bh[4], bl[4];
                LDM_X4(bh[0], bh[1], bh[2], bh[3], bd + BHI_O);
                LDM_X4(bl[0], bl[1], bl[2], bl[3], bd + BLO_O);
                #pragma unroll
                for (int q = 0; q < 2; q++) {
                    const int nf = 2 * p + q;
                    #pragma unroll
                    for (int mf = 0; mf < 2; mf++) {
                        mma_bf16(acc[mf][nf], ah[mf], bh[2*q], bh[2*q+1]);
                        mma_bf16(acc[mf][nf], ah[mf], bl[2*q], bl[2*q+1]);
                        mma_bf16(acc[mf][nf], al[mf], bh[2*q], bh[2*q+1]);
                    }
                }
            }
        }
        __syncthreads();
    }

    #pragma unroll
    for (int mf = 0; mf < 2; mf++) {
        const int row = m0 + wm * 32 + mf * 16 + grp;
        #pragma unroll
        for (int nf = 0; nf < 8; nf++) {
            const int nn = n0 + wn * 64 + nf * 8 + tig * 2;
            if (nn + 1 < PST) {
                float* p0 = Cout + (size_t)row * PST + nn;
                float* p1 = Cout + (size_t)(row + 8) * PST + nn;
                *(float2*)p0 = make_float2(acc[mf][nf][0], acc[mf][nf][1]);
                *(float2*)p1 = make_float2(acc[mf][nf][2], acc[mf][nf][3]);
            }
        }
    }
}

// ---------------------------------------------------------------------------
// Kernel 2: tensorized span head with single-sync double buffering.
// Per (batch, 128-pair chunk): Ht = relu(P[vi]+Q[vj]+ind*w1c+b1) (split bf16),
// logits = Ht @ W2 (mma m16n8k16, 3-term) + b2, fused log_softmax.
// Pipeline: iter ch issues LDGs for chunk ch+1 -> regs, mma on stage[ch&1],
// convert+STS into stage[(ch+1)&1], one __syncthreads.
// ---------------------------------------------------------------------------
#define SP_NCH   25
#define SP_STAGE 28160
#define AHT_HI   0
#define AHT_LO   10240
#define W2H_O    20480
#define W2L_O    24320
#define WS1C_O   (2 * SP_STAGE)        // 56320
#define SB1_O    (WS1C_O + 832 * 4)    // 59648
#define SRI_O    (SB1_O + 832 * 4)     // 62976
#define SRJ_O    (SRI_O + 512)         // 63488
#define SIND_O   (SRJ_O + 512)         // 64000
#define SP_DSM   (SIND_O + 512)        // 64512

__global__ __launch_bounds__(256, 2)
void span_head_tensor(const float* __restrict__ W1, const float* __restrict__ bias1,
                      const float* __restrict__ bias2,
                      const int* __restrict__ spans, float* __restrict__ out) {
    extern __shared__ __align__(16) unsigned char dsm[];
    const uint32_t sb = smem_u32(dsm);
    float* ws1c = (float*)(dsm + WS1C_O);
    float* sb1  = (float*)(dsm + SB1_O);
    int*   s_ri = (int*)(dsm + SRI_O);
    int*   s_rj = (int*)(dsm + SRJ_O);
    float* s_in = (float*)(dsm + SIND_O);

    const int b   = blockIdx.y;
    const int p0  = blockIdx.x * 128;
    const int tid = threadIdx.x;
    const int wid = tid >> 5;
    const int lid = tid & 31;
    const int grp = lid >> 2;
    const int tig = lid & 3;

    const float* w1c = W1 + (size_t)2 * DIM * NH1;

    // w1c / b1 into smem, zero-padded to 832 (kills all k-tail guards).
    for (int idx = tid; idx < 832; idx += 256) {
        ws1c[idx] = (idx < NH1) ? w1c[idx]   : 0.f;
        sb1[idx]  = (idx < NH1) ? bias1[idx] : 0.f;
    }
    // Analytic pair decode (nonzero order of (j>=i, j-i<30) band, L=128).
    if (tid < 128) {
        int p  = p0 + tid;
        int pc = (p < NPAIR) ? p : (NPAIR - 1);
        int i, j;
        if (pc < 2970) {
            i = pc / 30;
            j = i + (pc - 30 * i);
        } else {
            int q = pc - 2970;
            int d = (int)(29.5f - sqrtf(870.25f - 2.0f * (float)q));
            while ((d + 1) * (58 - d) / 2 <= q) d++;
            while (d * (59 - d) / 2 > q) d--;
            i = 99 + d;
            j = i + (q - d * (59 - d) / 2);
        }
        float ind = 0.f;
        if (p < NPAIR) {
            int s = spans[b*2 + 0];
            int e = spans[b*2 + 1];
            if (i == s && j == e)      ind = 2.f;
            else if (i >= s && j <= e) ind = 1.f;
        }
        s_ri[tid] = (b * SEQL + i) * PST;
        s_rj[tid] = (b * SEQL + j) * PST;
        s_in[tid] = ind;
    }
    __syncthreads();

    const int g_kq = tid & 7;    // k quad within 32-wide slab
    const int g_r0 = tid >> 3;   // pair rows g_r0 + 32w
    // Hoist this thread's 4 gather rows into registers.
    int   ri[4], rj[4];
    float indv[4];
    #pragma unroll
    for (int w = 0; w < 4; w++) {
        int r = g_r0 + w * 32;
        ri[w] = s_ri[r]; rj[w] = s_rj[r]; indv[w] = s_in[r];
    }

    const int a_lrow = lid & 15;
    const int a_lk   = (lid >> 4) << 3;
    const int b_lrow = (lid & 7) + ((lid >> 4) << 3);
    const int b_lk   = ((lid >> 3) & 1) << 3;

    float acc[5][4];
    #pragma unroll
    for (int nf = 0; nf < 5; nf++)
        #pragma unroll
        for (int c = 0; c < 4; c++) acc[nf][c] = 0.f;

    // ---- prologue: build stage 0 (chunk 0) ----
    {
        const int kb = g_kq * 4;   // < 32, always valid
        float4 c1 = *(const float4*)(ws1c + kb);
        float4 c2 = *(const float4*)(sb1 + kb);
        #pragma unroll
        for (int w = 0; w < 4; w++) {
            int r = g_r0 + w * 32;
            float4 p4 = *(const float4*)(g_P + ri[w] + kb);
            float4 q4 = *(const float4*)(g_Q + rj[w] + kb);
            float v0 = fmaxf(fmaf(indv[w], c1.x, p4.x + q4.x + c2.x), 0.f);
            float v1 = fmaxf(fmaf(indv[w], c1.y, p4.y + q4.y + c2.y), 0.f);
            float v2 = fmaxf(fmaf(indv[w], c1.z, p4.z + q4.z + c2.z), 0.f);
            float v3 = fmaxf(fmaf(indv[w], c1.w, p4.w + q4.w + c2.w), 0.f);
            uint32_t hw0, lw0, hw1, lw1;
            split2(v0, v1, hw0, lw0);
            split2(v2, v3, hw1, lw1);
            uint32_t ro = r * RS + g_kq * 8;
            *(uint2*)(dsm + AHT_HI + ro) = make_uint2(hw0, hw1);
            *(uint2*)(dsm + AHT_LO + ro) = make_uint2(lw0, lw1);
        }
        #pragma unroll
        for (int u = 0; u < 3; u++) {
            int w = tid + 256 * u;
            int n = w >> 4, kw = w & 15;
            *(uint32_t*)(dsm + W2H_O + n * RS + kw * 4) = g_W2h[w];
            *(uint32_t*)(dsm + W2L_O + n * RS + kw * 4) = g_W2l[w];
        }
    }
    __syncthreads();

    // ---- main loop ----
    for (int ch = 0; ch < SP_NCH; ch++) {
        const int cur = ch & 1;
        const bool has_next = (ch + 1 < SP_NCH);
        const int kb_n = (ch + 1) * 32 + g_kq * 4;

        // 1) issue global loads for chunk ch+1 (overlap with mma below)
        float4 pp[4], qq[4];
        uint32_t wh[3], wl[3];
        if (has_next) {
            if (kb_n < PST) {
                #pragma unroll
                for (int w = 0; w < 4; w++) {
                    pp[w] = *(const float4*)(g_P + ri[w] + kb_n);
                    qq[w] = *(const float4*)(g_Q + rj[w] + kb_n);
                }
            } else {
                #pragma unroll
                for (int w = 0; w < 4; w++) {
                    pp[w] = make_float4(0.f, 0.f, 0.f, 0.f);
                    qq[w] = make_float4(0.f, 0.f, 0.f, 0.f);
                }
            }
            const uint32_t* srcH = g_W2h + (ch + 1) * 768;
            const uint32_t* srcL = g_W2l + (ch + 1) * 768;
            #pragma unroll
            for (int u = 0; u < 3; u++) {
                wh[u] = srcH[tid + 256 * u];
                wl[u] = srcL[tid + 256 * u];
            }
        }

        // 2) mma on stage cur
        const uint32_t base = sb + cur * SP_STAGE;
        #pragma unroll
        for (int h = 0; h < 2; h++) {
            const int ks = h * 16;
            uint32_t ah[4], al[4];
            const uint32_t ad = base + (wid * 16 + a_lrow) * RS + (ks + a_lk) * 2;
            LDM_X4(ah[0], ah[1], ah[2], ah[3], ad + AHT_HI);
            LDM_X4(al[0], al[1], al[2], al[3], ad + AHT_LO);
            #pragma unroll
            for (int p = 0; p < 3; p++) {
                const uint32_t bd = base + (p * 16 + b_lrow) * RS + (ks + b_lk) * 2;
                uint32_t bh[4], bl[4];
                LDM_X4(bh[0], bh[1], bh[2], bh[3], bd + W2H_O);
                LDM_X4(bl[0], bl[1], bl[2], bl[3], bd + W2L_O);
                const int nq = (p < 2) ? 2 : 1;
                #pragma unroll
                for (int q = 0; q < 2; q++) {
                    if (q >= nq) break;
                    const int nf = 2 * p + q;
                    mma_bf16(acc[nf], ah, bh[2*q], bh[2*q+1]);
                    mma_bf16(acc[nf], ah, bl[2*q], bl[2*q+1]);
                    mma_bf16(acc[nf], al, bh[2*q], bh[2*q+1]);
                }
            }
        }

        // 3) convert + store chunk ch+1 into the other stage
        if (has_next) {
            unsigned char* nxt = dsm + ((ch + 1) & 1) * SP_STAGE;
            float4 c1 = *(const float4*)(ws1c + kb_n);   // zeros past 770
            float4 c2 = *(const float4*)(sb1 + kb_n);
            #pragma unroll
            for (int w = 0; w < 4; w++) {
                int r = g_r0 + w * 32;
                float v0 = fmaxf(fmaf(indv[w], c1.x, pp[w].x + qq[w].x + c2.x), 0.f);
                float v1 = fmaxf(fmaf(indv[w], c1.y, pp[w].y + qq[w].y + c2.y), 0.f);
                float v2 = fmaxf(fmaf(indv[w], c1.z, pp[w].z + qq[w].z + c2.z), 0.f);
                float v3 = fmaxf(fmaf(indv[w], c1.w, pp[w].w + qq[w].w + c2.w), 0.f);
                uint32_t hw0, lw0, hw1, lw1;
                split2(v0, v1, hw0, lw0);
                split2(v2, v3, hw1, lw1);
                uint32_t ro = r * RS + g_kq * 8;
                *(uint2*)(nxt + AHT_HI + ro) = make_uint2(hw0, hw1);
                *(uint2*)(nxt + AHT_LO + ro) = make_uint2(lw0, lw1);
            }
            #pragma unroll
            for (int u = 0; u < 3; u++) {
                int w = tid + 256 * u;
                int n = w >> 4, kw = w & 15;
                *(uint32_t*)(nxt + W2H_O + n * RS + kw * 4) = wh[u];
                *(uint32_t*)(nxt + W2L_O + n * RS + kw * 4) = wl[u];
            }
        }
        __syncthreads();
    }

    // ---- bias + log_softmax (4-lane butterfly over tig) + store ----
    float bb[10];
    #pragma unroll
    for (int nf = 0; nf < 5; nf++) {
        bb[2*nf + 0] = bias2[nf * 8 + tig * 2 + 0];
        bb[2*nf + 1] = bias2[nf * 8 + tig * 2 + 1];
    }
    #pragma unroll
    for (int rr = 0; rr < 2; rr++) {
        float l[10];
        #pragma unroll
        for (int nf = 0; nf < 5; nf++) {
            l[2*nf + 0] = acc[nf][2*rr + 0] + bb[2*nf + 0];
            l[2*nf + 1] = acc[nf][2*rr + 1] + bb[2*nf + 1];
        }
        float mx = l[0];
        #pragma unroll
        for (int j = 1; j < 10; j++) mx = fmaxf(mx, l[j]);
        mx = fmaxf(mx, __shfl_xor_sync(0xffffffffu, mx, 1));
        mx = fmaxf(mx, __shfl_xor_sync(0xffffffffu, mx, 2));
        float sm = 0.f;
        #pragma unroll
        for (int j = 0; j < 10; j++) sm += expf(l[j] - mx);
        sm += __shfl_xor_sync(0xffffffffu, sm, 1);
        sm += __shfl_xor_sync(0xffffffffu, sm, 2);
        float lse = mx + logf(sm);

        int p_row = p0 + wid * 16 + grp + 8 * rr;
        if (p_row < NPAIR) {
            float* op = out + ((size_t)b * NPAIR + p_row) * NOUT;
            #pragma unroll
            for (int nf = 0; nf < 5; nf++) {
                float2 v = make_float2(l[2*nf] - lse, l[2*nf + 1] - lse);
                *(float2*)(op + nf * 8 + tig * 2) = v;
            }
        }
    }
}

// ---------------------------------------------------------------------------
// Launch. Inputs (metadata order): hidden_states, pred_spans, token_num,
// span_available_indication_matrix, W1, b1, W2, b2. Output fp32 [16,3405,40].
// ---------------------------------------------------------------------------
extern "C" void kernel_launch(void* const* d_in, const int* in_sizes, int n_in,
                              void* d_out, int out_size) {
    const float* hidden = (const float*)d_in[0];
    const int*   spans  = (const int*)d_in[1];
    const float* W1 = (const float*)d_in[4];
    const float* b1 = (const float*)d_in[5];
    const float* W2 = (const float*)d_in[6];
    const float* b2 = (const float*)d_in[7];
    float* out = (float*)d_out;

    cudaFuncSetAttribute(span_head_tensor,
                         cudaFuncAttributeMaxDynamicSharedMemorySize, SP_DSM);

    prep_w2<<<75, 256>>>(W2);
    gemm1_mma<<<dim3(7, (BATCH * SEQL) / 128, 2), 256>>>(hidden, W1);
    span_head_tensor<<<dim3(27, BATCH), 256, SP_DSM>>>(W1, b1, b2, spans, out);
}

// round 13
// speedup vs baseline: 1.5203x; 1.0988x over previous
#include <cuda_runtime.h>
#include <cuda_bf16.h>
#include <math.h>
#include <stdint.h>

// Shapes (fixed for this problem)
#define BATCH 16
#define SEQL  128
#define DIM   768
#define NH1   770
#define NOUT  40
#define NPAIR 3405
#define LP1   129     // L+1 rows per batch in hidden_states
#define PST   772     // padded row stride for P/Q (float4-aligned)

// Scratch: P = X @ W1i, Q = X @ W1j (X = hidden[:,1:129,:] flattened, 2048 rows).
__device__ float g_P[(size_t)BATCH * SEQL * PST + 64];
__device__ float g_Q[(size_t)BATCH * SEQL * PST + 64];
// Precomputed split-bf16 W2 tiles for span head: [chunk(25)][n(48)][kword(16)].
__device__ uint32_t g_W2h[25 * 768];
__device__ uint32_t g_W2l[25 * 768];
// Precomputed split-bf16 A (hidden rows): [row(2048)][kword(384)].
__device__ __align__(16) uint32_t g_Ah[2048 * 384];
__device__ __align__(16) uint32_t g_Al[2048 * 384];
// Precomputed split-bf16 B (W1 halves, transposed): [z(2)][n(864 pad)][kword(384)].
__device__ __align__(16) uint32_t g_Bh[2 * 864 * 384];
__device__ __align__(16) uint32_t g_Bl[2 * 864 * 384];

// ---------------------------------------------------------------------------
// Helpers
// ---------------------------------------------------------------------------
__device__ __forceinline__ uint32_t smem_u32(const void* p) {
    uint32_t a;
    asm("{ .reg .u64 t; cvta.to.shared.u64 t, %1; cvt.u32.u64 %0, t; }" : "=r"(a) : "l"(p));
    return a;
}
#define LDM_X4(r0, r1, r2, r3, addr) \
    asm volatile("ldmatrix.sync.aligned.m8n8.x4.shared.b16 {%0,%1,%2,%3}, [%4];" \
                 : "=r"(r0), "=r"(r1), "=r"(r2), "=r"(r3) : "r"(addr))

__device__ __forceinline__ void mma_bf16(float* d, const uint32_t* a,
                                         uint32_t b0, uint32_t b1) {
    asm volatile(
        "mma.sync.aligned.m16n8k16.row.col.f32.bf16.bf16.f32 "
        "{%0,%1,%2,%3}, {%4,%5,%6,%7}, {%8,%9}, {%0,%1,%2,%3};\n"
        : "+f"(d[0]), "+f"(d[1]), "+f"(d[2]), "+f"(d[3])
        : "r"(a[0]), "r"(a[1]), "r"(a[2]), "r"(a[3]), "r"(b0), "r"(b1));
}
__device__ __forceinline__ void split2(float x0, float x1, uint32_t& hw, uint32_t& lw) {
    __nv_bfloat16 h0 = __float2bfloat16_rn(x0);
    __nv_bfloat16 h1 = __float2bfloat16_rn(x1);
    float l0 = x0 - __bfloat162float(h0);
    float l1 = x1 - __bfloat162float(h1);
    __nv_bfloat16 g0 = __float2bfloat16_rn(l0);
    __nv_bfloat16 g1 = __float2bfloat16_rn(l1);
    hw = (uint32_t)__bfloat16_as_ushort(h0) | ((uint32_t)__bfloat16_as_ushort(h1) << 16);
    lw = (uint32_t)__bfloat16_as_ushort(g0) | ((uint32_t)__bfloat16_as_ushort(g1) << 16);
}

// ---------------------------------------------------------------------------
// Kernel 0 (merged prep): block-range dispatch.
//   [0, 3072)      : split A       (2048 rows x 384 kwords)
//   [3072, 3744)   : split+transpose B (2 z x 24 ktiles x 14 ntiles of 64)
//   [3744, 3819)   : split W2 tiles for span head
// ---------------------------------------------------------------------------
#define PREP_A_BLKS  3072
#define PREP_B_BLKS  672
#define PREP_W2_BLKS 75

__global__ void prep_all(const float* __restrict__ hidden,
                         const float* __restrict__ W1,
                         const float* __restrict__ W2) {
    __shared__ float ts[32][65];
    const int blk = blockIdx.x;
    const int tid = threadIdx.x;

    if (blk < PREP_A_BLKS) {
        // ---- A split: word idx = row*384 + kw; floats 2kw, 2kw+1 ----
        int idx = blk * 256 + tid;              // < 786432 exactly
        int row = idx / 384;
        int kw  = idx - row * 384;
        int bb = row >> 7, t = row & 127;
        const float* src = hidden + ((size_t)bb * LP1 + t + 1) * DIM + kw * 2;
        float2 v = *(const float2*)src;
        uint32_t hw, lw;
        split2(v.x, v.y, hw, lw);
        g_Ah[idx] = hw;
        g_Al[idx] = lw;
    } else if (blk < PREP_A_BLKS + PREP_B_BLKS) {
        // ---- B split+transpose: tile 32k x 64n via smem ----
        int bid = blk - PREP_A_BLKS;            // 0..671
        int z   = bid / 336;
        int t2  = bid - z * 336;
        int kt  = t2 % 24;
        int nt  = t2 / 24;                      // 0..13
        int k0  = kt * 32;
        int n0  = nt * 64;
        const float* W = W1 + (size_t)z * DIM * NH1;

        int nx = tid & 63;
        int ky0 = tid >> 6;                     // 0..3
        #pragma unroll
        for (int s = 0; s < 8; s++) {
            int ky = ky0 + 4 * s;
            int n  = n0 + nx;
            ts[ky][nx] = (n < NH1) ? W[(size_t)(k0 + ky) * NH1 + n] : 0.f;
        }
        __syncthreads();
        int kx  = tid & 15;
        int ny0 = tid >> 4;                     // 0..15
        #pragma unroll
        for (int s = 0; s < 4; s++) {
            int ny = ny0 + 16 * s;
            int n  = n0 + ny;
            if (n < 864) {
                uint32_t hw, lw;
                split2(ts[2*kx][ny], ts[2*kx+1][ny], hw, lw);
                size_t gidx = ((size_t)z * 864 + n) * 384 + kt * 16 + kx;
                g_Bh[gidx] = hw;
                g_Bl[gidx] = lw;
            }
        }
    } else {
        // ---- W2 split tiles: idx = ch*768 + n*16 + kw ----
        int idx = (blk - PREP_A_BLKS - PREP_B_BLKS) * 256 + tid;
        if (idx >= 25 * 768) return;
        int ch = idx / 768, rem = idx - ch * 768;
        int n = rem >> 4, kw = rem & 15;
        int k = ch * 32 + kw * 2;
        float x0 = 0.f, x1 = 0.f;
        if (n < NOUT) {
            if (k     < NH1) x0 = W2[(size_t)k       * NOUT + n];
            if (k + 1 < NH1) x1 = W2[(size_t)(k + 1) * NOUT + n];
        }
        uint32_t hw, lw;
        split2(x0, x1, hw, lw);
        g_W2h[idx] = hw;
        g_W2l[idx] = lw;
    }
}

// ---------------------------------------------------------------------------
// Kernel 1: 2048 x 864(pad of 770) x 768 GEMM, bf16 m16n8k16 + ldmatrix,
// 3-term split (inputs pre-split by prep_all). z=0 -> P, z=1 -> Q.
// Block 128(M) x 96(N), 256 thr = 8 warps (4M x 2N), warp tile 32x48, BK=32.
// Grid = 9*16*2 = 288 blocks at occ 2 -> one balanced wave on 148 SMs.
// ---------------------------------------------------------------------------
#define G_BK  32
#define G_NKT (DIM / G_BK)   // 24
#define RS    80             // smem row stride in bytes
#define AHI_O 0
#define ALO_O (128 * RS)     // 10240
#define BHI_O (2 * 128 * RS) // 20480
#define BLO_O (BHI_O + 96 * RS)  // 28160; total 35840 B

__global__ __launch_bounds__(256, 2)
void gemm1_mma(void) {
    __shared__ __align__(16) unsigned char smbuf[BLO_O + 96 * RS];
    const uint32_t sb = smem_u32(smbuf);

    const int tid = threadIdx.x;
    const int wid = tid >> 5;
    const int lid = tid & 31;
    const int grp = lid >> 2;
    const int tig = lid & 3;
    const int wm  = wid & 3;    // warp M index (32 rows)
    const int wn  = wid >> 2;   // warp N index (48 cols)

    const int n0 = blockIdx.x * 96;
    const int m0 = blockIdx.y * 128;
    const int z  = blockIdx.z;
    float* Cout = (z == 0) ? g_P : g_Q;

    float acc[2][6][4];
    #pragma unroll
    for (int mf = 0; mf < 2; mf++)
        #pragma unroll
        for (int nf = 0; nf < 6; nf++)
            #pragma unroll
            for (int c = 0; c < 4; c++) acc[mf][nf][c] = 0.f;

    // A loader: thread t -> rows (t>>2)+64p, word-quad (t&3) of 16-word slab.
    const int a_q = tid & 3;
    const int a_r = tid >> 2;
    // B loader: thread t -> rows (t>>3)+32p, word-pair (t&7)*2.
    const int b_w8 = tid & 7;
    const int b_r  = tid >> 3;
    const size_t bbase = ((size_t)z * 864 + n0) * 384;

    const int a_lrow = lid & 15;
    const int a_lk   = (lid >> 4) << 3;
    const int b_lrow = (lid & 7) + ((lid >> 4) << 3);
    const int b_lk   = ((lid >> 3) & 1) << 3;

    for (int kt = 0; kt < G_NKT; kt++) {
        const int kw0 = kt * 16;
        // ---- A tile: 128 rows x 16 words, hi+lo, LDG.128 -> STS.128 ----
        #pragma unroll
        for (int p = 0; p < 2; p++) {
            const int row = a_r + 64 * p;
            const size_t gidx = (size_t)(m0 + row) * 384 + kw0 + a_q * 4;
            uint4 h = *(const uint4*)(g_Ah + gidx);
            uint4 l = *(const uint4*)(g_Al + gidx);
            *(uint4*)(smbuf + AHI_O + row * RS + a_q * 16) = h;
            *(uint4*)(smbuf + ALO_O + row * RS + a_q * 16) = l;
        }
        // ---- B tile: 96 n-rows x 16 words, hi+lo, LDG.64 -> STS.64 ----
        #pragma unroll
        for (int p = 0; p < 3; p++) {
            const int row = b_r + 32 * p;
            const size_t gidx = bbase + (size_t)row * 384 + kw0 + b_w8 * 2;
            uint2 h = *(const uint2*)(g_Bh + gidx);
            uint2 l = *(const uint2*)(g_Bl + gidx);
            *(uint2*)(smbuf + BHI_O + row * RS + b_w8 * 8) = h;
            *(uint2*)(smbuf + BLO_O + row * RS + b_w8 * 8) = l;
        }
        __syncthreads();

        #pragma unroll
        for (int h = 0; h < 2; h++) {
            const int ks = h * 16;
            uint32_t ah[2][4], al[2][4];
            #pragma unroll
            for (int mf = 0; mf < 2; mf++) {
                const uint32_t ad = sb + (wm * 32 + mf * 16 + a_lrow) * RS
                                       + (ks + a_lk) * 2;
                LDM_X4(ah[mf][0], ah[mf][1], ah[mf][2], ah[mf][3], ad + AHI_O);
                LDM_X4(al[mf][0], al[mf][1], al[mf][2], al[mf][3], ad + ALO_O);
            }
            #pragma unroll
            for (int p = 0; p < 3; p++) {
                const uint32_t bd = sb + (wn * 48 + p * 16 + b_lrow) * RS
                                       + (ks + b_lk) * 2;
                uint32_t bh[4], bl[4];
                LDM_X4(bh[0], bh[1], bh[2], bh[3], bd + BHI_O);
                LDM_X4(bl[0], bl[1], bl[2], bl[3], bd + BLO_O);
                #pragma unroll
                for (int q = 0; q < 2; q++) {
                    const int nf = 2 * p + q;
                    #pragma unroll
                    for (int mf = 0; mf < 2; mf++) {
                        mma_bf16(acc[mf][nf], ah[mf], bh[2*q], bh[2*q+1]);
                        mma_bf16(acc[mf][nf], ah[mf], bl[2*q], bl[2*q+1]);
                        mma_bf16(acc[mf][nf], al[mf], bh[2*q], bh[2*q+1]);
                    }
                }
            }
        }
        __syncthreads();
    }

    // Epilogue: d0,d1 -> (row, 2*tig..+1); d2,d3 -> (row+8, ...).
    // B cols >= 770 were prepped as zeros -> pad cols 770/771 get zeros.
    #pragma unroll
    for (int mf = 0; mf < 2; mf++) {
        const int row = m0 + wm * 32 + mf * 16 + grp;
        #pragma unroll
        for (int nf = 0; nf < 6; nf++) {
            const int nn = n0 + wn * 48 + nf * 8 + tig * 2;
            if (nn + 1 < PST) {
                float* p0 = Cout + (size_t)row * PST + nn;
                float* p1 = Cout + (size_t)(row + 8) * PST + nn;
                *(float2*)p0 = make_float2(acc[mf][nf][0], acc[mf][nf][1]);
                *(float2*)p1 = make_float2(acc[mf][nf][2], acc[mf][nf][3]);
            }
        }
    }
}

// ---------------------------------------------------------------------------
// Kernel 2 (unchanged from R11): tensorized span head, single-sync double
// buffering. Ht = relu(P[vi]+Q[vj]+ind*w1c+b1) split bf16; logits = Ht @ W2
// (mma m16n8k16, 3-term) + b2; fused log_softmax.
// ---------------------------------------------------------------------------
#define SP_NCH   25
#define SP_STAGE 28160
#define AHT_HI   0
#define AHT_LO   10240
#define W2H_O    20480
#define W2L_O    24320
#define WS1C_O   (2 * SP_STAGE)
#define SB1_O    (WS1C_O + 832 * 4)
#define SRI_O    (SB1_O + 832 * 4)
#define SRJ_O    (SRI_O + 512)
#define SIND_O   (SRJ_O + 512)
#define SP_DSM   (SIND_O + 512)        // 64512

__global__ __launch_bounds__(256, 2)
void span_head_tensor(const float* __restrict__ W1, const float* __restrict__ bias1,
                      const float* __restrict__ bias2,
                      const int* __restrict__ spans, float* __restrict__ out) {
    extern __shared__ __align__(16) unsigned char dsm[];
    const uint32_t sb = smem_u32(dsm);
    float* ws1c = (float*)(dsm + WS1C_O);
    float* sb1  = (float*)(dsm + SB1_O);
    int*   s_ri = (int*)(dsm + SRI_O);
    int*   s_rj = (int*)(dsm + SRJ_O);
    float* s_in = (float*)(dsm + SIND_O);

    const int b   = blockIdx.y;
    const int p0  = blockIdx.x * 128;
    const int tid = threadIdx.x;
    const int wid = tid >> 5;
    const int lid = tid & 31;
    const int grp = lid >> 2;
    const int tig = lid & 3;

    const float* w1c = W1 + (size_t)2 * DIM * NH1;

    for (int idx = tid; idx < 832; idx += 256) {
        ws1c[idx] = (idx < NH1) ? w1c[idx]   : 0.f;
        sb1[idx]  = (idx < NH1) ? bias1[idx] : 0.f;
    }
    if (tid < 128) {
        int p  = p0 + tid;
        int pc = (p < NPAIR) ? p : (NPAIR - 1);
        int i, j;
        if (pc < 2970) {
            i = pc / 30;
            j = i + (pc - 30 * i);
        } else {
            int q = pc - 2970;
            int d = (int)(29.5f - sqrtf(870.25f - 2.0f * (float)q));
            while ((d + 1) * (58 - d) / 2 <= q) d++;
            while (d * (59 - d) / 2 > q) d--;
            i = 99 + d;
            j = i + (q - d * (59 - d) / 2);
        }
        float ind = 0.f;
        if (p < NPAIR) {
            int s = spans[b*2 + 0];
            int e = spans[b*2 + 1];
            if (i == s && j == e)      ind = 2.f;
            else if (i >= s && j <= e) ind = 1.f;
        }
        s_ri[tid] = (b * SEQL + i) * PST;
        s_rj[tid] = (b * SEQL + j) * PST;
        s_in[tid] = ind;
    }
    __syncthreads();

    const int g_kq = tid & 7;
    const int g_r0 = tid >> 3;
    int   ri[4], rj[4];
    float indv[4];
    #pragma unroll
    for (int w = 0; w < 4; w++) {
        int r = g_r0 + w * 32;
        ri[w] = s_ri[r]; rj[w] = s_rj[r]; indv[w] = s_in[r];
    }

    const int a_lrow = lid & 15;
    const int a_lk   = (lid >> 4) << 3;
    const int b_lrow = (lid & 7) + ((lid >> 4) << 3);
    const int b_lk   = ((lid >> 3) & 1) << 3;

    float acc[5][4];
    #pragma unroll
    for (int nf = 0; nf < 5; nf++)
        #pragma unroll
        for (int c = 0; c < 4; c++) acc[nf][c] = 0.f;

    {   // prologue: stage 0 (chunk 0)
        const int kb = g_kq * 4;
        float4 c1 = *(const float4*)(ws1c + kb);
        float4 c2 = *(const float4*)(sb1 + kb);
        #pragma unroll
        for (int w = 0; w < 4; w++) {
            int r = g_r0 + w * 32;
            float4 p4 = *(const float4*)(g_P + ri[w] + kb);
            float4 q4 = *(const float4*)(g_Q + rj[w] + kb);
            float v0 = fmaxf(fmaf(indv[w], c1.x, p4.x + q4.x + c2.x), 0.f);
            float v1 = fmaxf(fmaf(indv[w], c1.y, p4.y + q4.y + c2.y), 0.f);
            float v2 = fmaxf(fmaf(indv[w], c1.z, p4.z + q4.z + c2.z), 0.f);
            float v3 = fmaxf(fmaf(indv[w], c1.w, p4.w + q4.w + c2.w), 0.f);
            uint32_t hw0, lw0, hw1, lw1;
            split2(v0, v1, hw0, lw0);
            split2(v2, v3, hw1, lw1);
            uint32_t ro = r * RS + g_kq * 8;
            *(uint2*)(dsm + AHT_HI + ro) = make_uint2(hw0, hw1);
            *(uint2*)(dsm + AHT_LO + ro) = make_uint2(lw0, lw1);
        }
        #pragma unroll
        for (int u = 0; u < 3; u++) {
            int w = tid + 256 * u;
            int n = w >> 4, kw = w & 15;
            *(uint32_t*)(dsm + W2H_O + n * RS + kw * 4) = g_W2h[w];
            *(uint32_t*)(dsm + W2L_O + n * RS + kw * 4) = g_W2l[w];
        }
    }
    __syncthreads();

    for (int ch = 0; ch < SP_NCH; ch++) {
        const int cur = ch & 1;
        const bool has_next = (ch + 1 < SP_NCH);
        const int kb_n = (ch + 1) * 32 + g_kq * 4;

        float4 pp[4], qq[4];
        uint32_t wh[3], wl[3];
        if (has_next) {
            if (kb_n < PST) {
                #pragma unroll
                for (int w = 0; w < 4; w++) {
                    pp[w] = *(const float4*)(g_P + ri[w] + kb_n);
                    qq[w] = *(const float4*)(g_Q + rj[w] + kb_n);
                }
            } else {
                #pragma unroll
                for (int w = 0; w < 4; w++) {
                    pp[w] = make_float4(0.f, 0.f, 0.f, 0.f);
                    qq[w] = make_float4(0.f, 0.f, 0.f, 0.f);
                }
            }
            const uint32_t* srcH = g_W2h + (ch + 1) * 768;
            const uint32_t* srcL = g_W2l + (ch + 1) * 768;
            #pragma unroll
            for (int u = 0; u < 3; u++) {
                wh[u] = srcH[tid + 256 * u];
                wl[u] = srcL[tid + 256 * u];
            }
        }

        const uint32_t base = sb + cur * SP_STAGE;
        #pragma unroll
        for (int h = 0; h < 2; h++) {
            const int ks = h * 16;
            uint32_t ah[4], al[4];
            const uint32_t ad = base + (wid * 16 + a_lrow) * RS + (ks + a_lk) * 2;
            LDM_X4(ah[0], ah[1], ah[2], ah[3], ad + AHT_HI);
            LDM_X4(al[0], al[1], al[2], al[3], ad + AHT_LO);
            #pragma unroll
            for (int p = 0; p < 3; p++) {
                const uint32_t bd = base + (p * 16 + b_lrow) * RS + (ks + b_lk) * 2;
                uint32_t bh[4], bl[4];
                LDM_X4(bh[0], bh[1], bh[2], bh[3], bd + W2H_O);
                LDM_X4(bl[0], bl[1], bl[2], bl[3], bd + W2L_O);
                const int nq = (p < 2) ? 2 : 1;
                #pragma unroll
                for (int q = 0; q < 2; q++) {
                    if (q >= nq) break;
                    const int nf = 2 * p + q;
                    mma_bf16(acc[nf], ah, bh[2*q], bh[2*q+1]);
                    mma_bf16(acc[nf], ah, bl[2*q], bl[2*q+1]);
                    mma_bf16(acc[nf], al, bh[2*q], bh[2*q+1]);
                }
            }
        }

        if (has_next) {
            unsigned char* nxt = dsm + ((ch + 1) & 1) * SP_STAGE;
            float4 c1 = *(const float4*)(ws1c + kb_n);
            float4 c2 = *(const float4*)(sb1 + kb_n);
            #pragma unroll
            for (int w = 0; w < 4; w++) {
                int r = g_r0 + w * 32;
                float v0 = fmaxf(fmaf(indv[w], c1.x, pp[w].x + qq[w].x + c2.x), 0.f);
                float v1 = fmaxf(fmaf(indv[w], c1.y, pp[w].y + qq[w].y + c2.y), 0.f);
                float v2 = fmaxf(fmaf(indv[w], c1.z, pp[w].z + qq[w].z + c2.z), 0.f);
                float v3 = fmaxf(fmaf(indv[w], c1.w, pp[w].w + qq[w].w + c2.w), 0.f);
                uint32_t hw0, lw0, hw1, lw1;
                split2(v0, v1, hw0, lw0);
                split2(v2, v3, hw1, lw1);
                uint32_t ro = r * RS + g_kq * 8;
                *(uint2*)(nxt + AHT_HI + ro) = make_uint2(hw0, hw1);
                *(uint2*)(nxt + AHT_LO + ro) = make_uint2(lw0, lw1);
            }
            #pragma unroll
            for (int u = 0; u < 3; u++) {
                int w = tid + 256 * u;
                int n = w >> 4, kw = w & 15;
                *(uint32_t*)(nxt + W2H_O + n * RS + kw * 4) = wh[u];
                *(uint32_t*)(nxt + W2L_O + n * RS + kw * 4) = wl[u];
            }
        }
        __syncthreads();
    }

    float bb[10];
    #pragma unroll
    for (int nf = 0; nf < 5; nf++) {
        bb[2*nf + 0] = bias2[nf * 8 + tig * 2 + 0];
        bb[2*nf + 1] = bias2[nf * 8 + tig * 2 + 1];
    }
    #pragma unroll
    for (int rr = 0; rr < 2; rr++) {
        float l[10];
        #pragma unroll
        for (int nf = 0; nf < 5; nf++) {
            l[2*nf + 0] = acc[nf][2*rr + 0] + bb[2*nf + 0];
            l[2*nf + 1] = acc[nf][2*rr + 1] + bb[2*nf + 1];
        }
        float mx = l[0];
        #pragma unroll
        for (int j = 1; j < 10; j++) mx = fmaxf(mx, l[j]);
        mx = fmaxf(mx, __shfl_xor_sync(0xffffffffu, mx, 1));
        mx = fmaxf(mx, __shfl_xor_sync(0xffffffffu, mx, 2));
        float sm = 0.f;
        #pragma unroll
        for (int j = 0; j < 10; j++) sm += expf(l[j] - mx);
        sm += __shfl_xor_sync(0xffffffffu, sm, 1);
        sm += __shfl_xor_sync(0xffffffffu, sm, 2);
        float lse = mx + logf(sm);

        int p_row = p0 + wid * 16 + grp + 8 * rr;
        if (p_row < NPAIR) {
            float* op = out + ((size_t)b * NPAIR + p_row) * NOUT;
            #pragma unroll
            for (int nf = 0; nf < 5; nf++) {
                float2 v = make_float2(l[2*nf] - lse, l[2*nf + 1] - lse);
                *(float2*)(op + nf * 8 + tig * 2) = v;
            }
        }
    }
}

// ---------------------------------------------------------------------------
// Launch. Inputs (metadata order): hidden_states, pred_spans, token_num,
// span_available_indication_matrix, W1, b1, W2, b2. Output fp32 [16,3405,40].
// ---------------------------------------------------------------------------
extern "C" void kernel_launch(void* const* d_in, const int* in_sizes, int n_in,
                              void* d_out, int out_size) {
    const float* hidden = (const float*)d_in[0];
    const int*   spans  = (const int*)d_in[1];
    const float* W1 = (const float*)d_in[4];
    const float* b1 = (const float*)d_in[5];
    const float* W2 = (const float*)d_in[6];
    const float* b2 = (const float*)d_in[7];
    float* out = (float*)d_out;

    cudaFuncSetAttribute(span_head_tensor,
                         cudaFuncAttributeMaxDynamicSharedMemorySize, SP_DSM);

    prep_all<<<PREP_A_BLKS + PREP_B_BLKS + PREP_W2_BLKS, 256>>>(hidden, W1, W2);
    gemm1_mma<<<dim3(9, (BATCH * SEQL) / 128, 2), 256>>>();
    span_head_tensor<<<dim3(27, BATCH), 256, SP_DSM>>>(W1, b1, b2, spans, out);
}